// round 1
// baseline (speedup 1.0000x reference)
#include <cuda_runtime.h>
#include <math.h>

// ---------------- problem constants ----------------
constexpr int CB   = 2;      // batch
constexpr int CT   = 2048;   // seq len
constexpr int CD   = 1024;   // model dim
constexpr int CNH  = 16;     // query heads
constexpr int CNKV = 4;      // kv heads
constexpr int CHD  = 64;     // head dim
constexpr int CHALF = 8;     // rope half
constexpr int CGROUPS = CNH / CNKV;      // 4
constexpr int CNQKV = (CNH + 2*CNKV)*CHD; // 1536
constexpr int CM = CB * CT;               // 4096

// ---------------- scratch (device globals; no allocation allowed) ----------------
__device__ float g_q[(size_t)CB*CNH*CT*CHD];   // 16 MB [b,h,t,d]
__device__ float g_k[(size_t)CB*CNKV*CT*CHD];  // 4 MB
__device__ float g_v[(size_t)CB*CNKV*CT*CHD];  // 4 MB
__device__ float g_ao[(size_t)CB*CT*CD];       // 16 MB [b,t, h*HD+d]

// =================================================================
// Kernel 1: QKV projection  C[m][n] = x[m][:] . w_qkv[n][:]
// 128x128x8 tile, 256 threads, 8x8 per-thread. Epilogue scatters to
// q/k/v layouts with q_scale / k_scale applied.
// =================================================================
__global__ __launch_bounds__(256) void qkv_gemm(const float* __restrict__ x,
                                                const float* __restrict__ w,
                                                const float* __restrict__ qsc,
                                                const float* __restrict__ ksc) {
    __shared__ float As[8][132];
    __shared__ float Bs[8][132];
    const int tid = threadIdx.x;
    const int tx = tid & 15, ty = tid >> 4;
    const int bm = blockIdx.y, bn = blockIdx.x;
    const int lrow = tid >> 1;
    const int lkg  = (tid & 1) * 4;
    const float* Ap = x + (size_t)(bm*128 + lrow)*CD + lkg;
    const float* Bp = w + (size_t)(bn*128 + lrow)*CD + lkg;

    float acc[8][8];
#pragma unroll
    for (int i = 0; i < 8; i++)
#pragma unroll
        for (int j = 0; j < 8; j++) acc[i][j] = 0.f;

    for (int kt = 0; kt < CD; kt += 8) {
        float4 av = *(const float4*)(Ap + kt);
        float4 bv = *(const float4*)(Bp + kt);
        __syncthreads();
        As[lkg+0][lrow] = av.x; As[lkg+1][lrow] = av.y;
        As[lkg+2][lrow] = av.z; As[lkg+3][lrow] = av.w;
        Bs[lkg+0][lrow] = bv.x; Bs[lkg+1][lrow] = bv.y;
        Bs[lkg+2][lrow] = bv.z; Bs[lkg+3][lrow] = bv.w;
        __syncthreads();
#pragma unroll
        for (int k = 0; k < 8; k++) {
            float a[8], bf[8];
            *(float4*)&a[0]  = *(const float4*)&As[k][ty*4];
            *(float4*)&a[4]  = *(const float4*)&As[k][ty*4 + 64];
            *(float4*)&bf[0] = *(const float4*)&Bs[k][tx*4];
            *(float4*)&bf[4] = *(const float4*)&Bs[k][tx*4 + 64];
#pragma unroll
            for (int i = 0; i < 8; i++)
#pragma unroll
                for (int j = 0; j < 8; j++) acc[i][j] += a[i]*bf[j];
        }
    }
    // epilogue: scatter into q/k/v with scales
#pragma unroll
    for (int i = 0; i < 8; i++) {
        int m = bm*128 + ty*4 + (i & 3) + (i >> 2)*64;
        int b = m >> 11;       // /T
        int t = m & (CT - 1);
#pragma unroll
        for (int j = 0; j < 8; j++) {
            int n = bn*128 + tx*4 + (j & 3) + (j >> 2)*64;
            float val = acc[i][j];
            if (n < CNH*CHD) {
                int h = n >> 6, d = n & 63;
                g_q[(((size_t)b*CNH + h)*CT + t)*CHD + d] = val * qsc[h];
            } else if (n < (CNH + CNKV)*CHD) {
                int n2 = n - CNH*CHD; int h = n2 >> 6, d = n2 & 63;
                g_k[(((size_t)b*CNKV + h)*CT + t)*CHD + d] = val * ksc[h];
            } else {
                int n2 = n - (CNH + CNKV)*CHD; int h = n2 >> 6, d = n2 & 63;
                g_v[(((size_t)b*CNKV + h)*CT + t)*CHD + d] = val;
            }
        }
    }
}

// =================================================================
// Kernel 2: RoPE in place on g_q and g_k (first 16 dims of each head)
// =================================================================
__global__ void rope_kernel(const float* __restrict__ cs, const float* __restrict__ sn) {
    int idx = blockIdx.x*blockDim.x + threadIdx.x;
    const int totQ = CB*CNH*CT*CHALF;
    const int tot  = totQ + CB*CNKV*CT*CHALF;
    if (idx >= tot) return;
    float* base = g_q;
    int li = idx;
    if (idx >= totQ) { base = g_k; li = idx - totQ; }
    int i  = li & 7;
    int t  = (li >> 3) & (CT - 1);
    int rh = li >> 14;                 // / (HALF*T)
    float* p = base + ((size_t)rh*CT + t)*CHD;
    float c = cs[t*CHALF + i], s = sn[t*CHALF + i];
    float x1 = p[i], x2 = p[i + CHALF];
    p[i]         = x1*c - x2*s;
    p[i + CHALF] = x1*s + x2*c;
}

// =================================================================
// Kernel 3: causal flash attention + fused v-projection epilogue.
// 64x64 tiles, 256 threads (16x16), 4x4 per-thread fragments.
// Shared: Qs[64][64], Ks[64][68] (aliased with P), Vs[64][64].
// =================================================================
__global__ __launch_bounds__(256) void attn_kernel() {
    extern __shared__ float smem[];
    float* Qs = smem;               // 64*64
    float* Ks = smem + 64*64;       // 64*68, reused as P after S compute
    float* Vs = Ks + 64*68;         // 64*64

    const int tid = threadIdx.x;
    const int tx = tid & 15, ty = tid >> 4;
    const int qb = blockIdx.x, h = blockIdx.y, b = blockIdx.z;
    const int kvh = h / CGROUPS;
    const float* qptr  = g_q + (((size_t)b*CNH + h)*CT + (size_t)qb*64)*CHD;
    const float* kbase = g_k + ((size_t)b*CNKV + kvh)*CT*CHD;
    const float* vbase = g_v + ((size_t)b*CNKV + kvh)*CT*CHD;

    // load Q tile with softmax scale folded in
    const float sc = 0.125f;  // HD^-0.5
    for (int it = tid; it < 64*16; it += 256) {
        int r = it >> 4, dg = (it & 15) << 2;
        float4 v4 = *(const float4*)(qptr + r*CHD + dg);
        v4.x *= sc; v4.y *= sc; v4.z *= sc; v4.w *= sc;
        *(float4*)&Qs[r*64 + dg] = v4;
    }

    float mst[4], lst[4], o[4][4];
#pragma unroll
    for (int i = 0; i < 4; i++) {
        mst[i] = -1e30f; lst[i] = 0.f;
#pragma unroll
        for (int j = 0; j < 4; j++) o[i][j] = 0.f;
    }

    for (int jb = 0; jb <= qb; jb++) {
        __syncthreads();   // prior PV finished reading Ks(P)/Vs
        for (int it = tid; it < 64*16; it += 256) {
            int r = it >> 4, dg = (it & 15) << 2;
            *(float4*)&Ks[r*68 + dg] = *(const float4*)(kbase + (size_t)(jb*64 + r)*CHD + dg);
            *(float4*)&Vs[r*64 + dg] = *(const float4*)(vbase + (size_t)(jb*64 + r)*CHD + dg);
        }
        __syncthreads();

        // S = Q K^T (inner product over d, float4 chunks)
        float s[4][4];
#pragma unroll
        for (int i = 0; i < 4; i++)
#pragma unroll
            for (int j = 0; j < 4; j++) s[i][j] = 0.f;
#pragma unroll
        for (int d = 0; d < 64; d += 4) {
            float4 qv[4], kv4[4];
#pragma unroll
            for (int i = 0; i < 4; i++) qv[i]  = *(const float4*)&Qs[(4*ty + i)*64 + d];
#pragma unroll
            for (int j = 0; j < 4; j++) kv4[j] = *(const float4*)&Ks[(4*tx + j)*68 + d];
#pragma unroll
            for (int i = 0; i < 4; i++)
#pragma unroll
                for (int j = 0; j < 4; j++)
                    s[i][j] += qv[i].x*kv4[j].x + qv[i].y*kv4[j].y
                             + qv[i].z*kv4[j].z + qv[i].w*kv4[j].w;
        }

        if (jb == qb) {   // causal mask on diagonal block
#pragma unroll
            for (int i = 0; i < 4; i++)
#pragma unroll
                for (int j = 0; j < 4; j++)
                    if (4*tx + j > 4*ty + i) s[i][j] = -1e30f;
        }

        // online softmax (row stats reduced over the 16-lane tx group)
#pragma unroll
        for (int i = 0; i < 4; i++) {
            float mx = fmaxf(fmaxf(s[i][0], s[i][1]), fmaxf(s[i][2], s[i][3]));
#pragma unroll
            for (int w = 8; w >= 1; w >>= 1) mx = fmaxf(mx, __shfl_xor_sync(0xffffffffu, mx, w));
            float mnew  = fmaxf(mst[i], mx);
            float alpha = __expf(mst[i] - mnew);
            mst[i] = mnew;
            float rs = 0.f;
#pragma unroll
            for (int j = 0; j < 4; j++) { s[i][j] = __expf(s[i][j] - mnew); rs += s[i][j]; }
#pragma unroll
            for (int w = 8; w >= 1; w >>= 1) rs += __shfl_xor_sync(0xffffffffu, rs, w);
            lst[i] = lst[i]*alpha + rs;
#pragma unroll
            for (int j = 0; j < 4; j++) o[i][j] *= alpha;
        }

        __syncthreads();   // everyone done reading Ks -> safe to overwrite with P
#pragma unroll
        for (int i = 0; i < 4; i++)
            *(float4*)&Ks[(4*ty + i)*68 + 4*tx] = make_float4(s[i][0], s[i][1], s[i][2], s[i][3]);
        __syncthreads();

        // O += P V
#pragma unroll 2
        for (int j = 0; j < 64; j++) {
            float4 vv = *(const float4*)&Vs[j*64 + 4*tx];
#pragma unroll
            for (int i = 0; i < 4; i++) {
                float p = Ks[(4*ty + i)*68 + j];
                o[i][0] += p*vv.x; o[i][1] += p*vv.y;
                o[i][2] += p*vv.z; o[i][3] += p*vv.w;
            }
        }
    }

    // epilogue: normalize + subtract projection onto v[t] (v at query index)
#pragma unroll
    for (int i = 0; i < 4; i++) {
        int t = qb*64 + 4*ty + i;
        float inv = 1.f / lst[i];
        float4 vq = *(const float4*)(vbase + (size_t)t*CHD + 4*tx);
        float ov0 = o[i][0]*inv, ov1 = o[i][1]*inv, ov2 = o[i][2]*inv, ov3 = o[i][3]*inv;
        float pd = ov0*vq.x + ov1*vq.y + ov2*vq.z + ov3*vq.w;
        float pn = vq.x*vq.x + vq.y*vq.y + vq.z*vq.z + vq.w*vq.w;
#pragma unroll
        for (int w = 8; w >= 1; w >>= 1) {
            pd += __shfl_xor_sync(0xffffffffu, pd, w);
            pn += __shfl_xor_sync(0xffffffffu, pn, w);
        }
        float coef = pd / fmaxf(pn, 1e-8f);
        float4 res = make_float4(ov0 - coef*vq.x, ov1 - coef*vq.y,
                                 ov2 - coef*vq.z, ov3 - coef*vq.w);
        *(float4*)(g_ao + ((size_t)b*CT + t)*CD + h*CHD + 4*tx) = res;
    }
}

// =================================================================
// Kernel 4: output projection out = ao @ w_out^T
// =================================================================
__global__ __launch_bounds__(256) void out_gemm(const float* __restrict__ w,
                                                float* __restrict__ out) {
    __shared__ float As[8][132];
    __shared__ float Bs[8][132];
    const int tid = threadIdx.x;
    const int tx = tid & 15, ty = tid >> 4;
    const int bm = blockIdx.y, bn = blockIdx.x;
    const int lrow = tid >> 1;
    const int lkg  = (tid & 1) * 4;
    const float* Ap = g_ao + (size_t)(bm*128 + lrow)*CD + lkg;
    const float* Bp = w    + (size_t)(bn*128 + lrow)*CD + lkg;

    float acc[8][8];
#pragma unroll
    for (int i = 0; i < 8; i++)
#pragma unroll
        for (int j = 0; j < 8; j++) acc[i][j] = 0.f;

    for (int kt = 0; kt < CD; kt += 8) {
        float4 av = *(const float4*)(Ap + kt);
        float4 bv = *(const float4*)(Bp + kt);
        __syncthreads();
        As[lkg+0][lrow] = av.x; As[lkg+1][lrow] = av.y;
        As[lkg+2][lrow] = av.z; As[lkg+3][lrow] = av.w;
        Bs[lkg+0][lrow] = bv.x; Bs[lkg+1][lrow] = bv.y;
        Bs[lkg+2][lrow] = bv.z; Bs[lkg+3][lrow] = bv.w;
        __syncthreads();
#pragma unroll
        for (int k = 0; k < 8; k++) {
            float a[8], bf[8];
            *(float4*)&a[0]  = *(const float4*)&As[k][ty*4];
            *(float4*)&a[4]  = *(const float4*)&As[k][ty*4 + 64];
            *(float4*)&bf[0] = *(const float4*)&Bs[k][tx*4];
            *(float4*)&bf[4] = *(const float4*)&Bs[k][tx*4 + 64];
#pragma unroll
            for (int i = 0; i < 8; i++)
#pragma unroll
                for (int j = 0; j < 8; j++) acc[i][j] += a[i]*bf[j];
        }
    }
#pragma unroll
    for (int i = 0; i < 8; i++) {
        int m = bm*128 + ty*4 + (i & 3) + (i >> 2)*64;
        float* dst = out + (size_t)m*CD + bn*128;
        *(float4*)(dst + tx*4)      = make_float4(acc[i][0], acc[i][1], acc[i][2], acc[i][3]);
        *(float4*)(dst + tx*4 + 64) = make_float4(acc[i][4], acc[i][5], acc[i][6], acc[i][7]);
    }
}

// =================================================================
extern "C" void kernel_launch(void* const* d_in, const int* in_sizes, int n_in,
                              void* d_out, int out_size) {
    (void)in_sizes; (void)n_in; (void)out_size;
    const float* x    = (const float*)d_in[0];
    const float* cs   = (const float*)d_in[1];
    const float* sn   = (const float*)d_in[2];
    // d_in[3] = attn_mask (causal tril) — implied by kernel structure
    const float* wqkv = (const float*)d_in[4];
    const float* wout = (const float*)d_in[5];
    const float* qsc  = (const float*)d_in[6];
    const float* ksc  = (const float*)d_in[7];
    float* out = (float*)d_out;

    dim3 g1(CNQKV/128, CM/128);            // 12 x 32
    qkv_gemm<<<g1, 256>>>(x, wqkv, qsc, ksc);

    int tot = (CB*CNH + CB*CNKV)*CT*CHALF;
    rope_kernel<<<(tot + 255)/256, 256>>>(cs, sn);

    size_t smemB = (size_t)(64*64 + 64*68 + 64*64)*sizeof(float);  // 50176 B
    cudaFuncSetAttribute(attn_kernel, cudaFuncAttributeMaxDynamicSharedMemorySize, (int)smemB);
    dim3 g2(CT/64, CNH, CB);               // 32 x 16 x 2
    attn_kernel<<<g2, 256, smemB>>>();

    dim3 g3(CD/128, CM/128);               // 8 x 32
    out_gemm<<<g3, 256>>>(wout, out);
}

// round 2
// speedup vs baseline: 3.2783x; 3.2783x over previous
#include <cuda_runtime.h>
#include <math.h>

// ---------------- problem constants ----------------
constexpr int CB   = 2;
constexpr int CT   = 2048;
constexpr int CD   = 1024;
constexpr int CNH  = 16;
constexpr int CNKV = 4;
constexpr int CHD  = 64;
constexpr int CHALF = 8;
constexpr int CGROUPS = CNH / CNKV;       // 4
constexpr int CNQKV = (CNH + 2*CNKV)*CHD; // 1536
constexpr int CM = CB * CT;               // 4096

// ---------------- scratch (device globals) ----------------
__device__ float g_q[(size_t)CB*CNH*CT*CHD];
__device__ float g_k[(size_t)CB*CNKV*CT*CHD];
__device__ float g_v[(size_t)CB*CNKV*CT*CHD];
__device__ float g_ao[(size_t)CB*CT*CD];

// ---------------- tf32 helpers ----------------
__device__ __forceinline__ unsigned f2tf(float x) {
    unsigned r; asm("cvt.rna.tf32.f32 %0, %1;" : "=r"(r) : "f"(x)); return r;
}
__device__ __forceinline__ void mma8(float* c, const unsigned* a, const unsigned* b) {
    asm volatile(
        "mma.sync.aligned.m16n8k8.row.col.f32.tf32.tf32.f32 "
        "{%0,%1,%2,%3},{%4,%5,%6,%7},{%8,%9},{%0,%1,%2,%3};"
        : "+f"(c[0]), "+f"(c[1]), "+f"(c[2]), "+f"(c[3])
        : "r"(a[0]), "r"(a[1]), "r"(a[2]), "r"(a[3]), "r"(b[0]), "r"(b[1]));
}

// =================================================================
// Dense GEMM (tf32 tensor cores): C[m][n] = A[m][:] . B[n][:]
// block 128x128, 8 warps (2m x 4n), warp tile 64x32, K-chunk 32.
// EPI==1: QKV scatter epilogue.  EPI==0: A = g_ao, plain store.
// =================================================================
__device__ __forceinline__ void scatter_qkv(int m, int n, float v0, float v1,
                                            const float* qsc, const float* ksc) {
    int b = m >> 11, t = m & (CT - 1);
    if (n < CNH*CHD) {
        int hh = n >> 6, d = n & 63; float s = qsc[hh];
        float* p = &g_q[(((size_t)b*CNH + hh)*CT + t)*CHD + d];
        p[0] = v0*s; p[1] = v1*s;
    } else if (n < (CNH + CNKV)*CHD) {
        int n2 = n - CNH*CHD; int hh = n2 >> 6, d = n2 & 63; float s = ksc[hh];
        float* p = &g_k[(((size_t)b*CNKV + hh)*CT + t)*CHD + d];
        p[0] = v0*s; p[1] = v1*s;
    } else {
        int n2 = n - (CNH + CNKV)*CHD; int hh = n2 >> 6, d = n2 & 63;
        float* p = &g_v[(((size_t)b*CNKV + hh)*CT + t)*CHD + d];
        p[0] = v0; p[1] = v1;
    }
}

template<int EPI>
__global__ __launch_bounds__(256) void gemm_tc(const float* __restrict__ A,
                                               const float* __restrict__ Bm,
                                               const float* __restrict__ qsc,
                                               const float* __restrict__ ksc,
                                               float* __restrict__ out) {
    __shared__ unsigned As[128*36];
    __shared__ unsigned Bs[128*36];
    const int tid = threadIdx.x, lane = tid & 31, warp = tid >> 5;
    const int wm = warp >> 2, wn = warp & 3;
    const int g = lane >> 2, t4 = lane & 3;
    const int bm = blockIdx.y, bn = blockIdx.x;

    const float* Ap = (EPI == 1) ? A : (const float*)g_ao;

    float acc[4][4][4];
#pragma unroll
    for (int mt = 0; mt < 4; mt++)
#pragma unroll
        for (int nt = 0; nt < 4; nt++)
#pragma unroll
            for (int c = 0; c < 4; c++) acc[mt][nt][c] = 0.f;

    for (int kt = 0; kt < CD; kt += 32) {
        float4 va[4], vb[4];
        int rows[4], cols[4];
#pragma unroll
        for (int r = 0; r < 4; r++) {
            int idx = tid + 256*r;
            rows[r] = idx >> 3; cols[r] = (idx & 7) << 2;
            va[r] = *(const float4*)(Ap + (size_t)(bm*128 + rows[r])*CD + kt + cols[r]);
            vb[r] = *(const float4*)(Bm + (size_t)(bn*128 + rows[r])*CD + kt + cols[r]);
        }
        __syncthreads();
#pragma unroll
        for (int r = 0; r < 4; r++) {
            unsigned* pa = &As[rows[r]*36 + cols[r]];
            pa[0] = f2tf(va[r].x); pa[1] = f2tf(va[r].y);
            pa[2] = f2tf(va[r].z); pa[3] = f2tf(va[r].w);
            unsigned* pb = &Bs[rows[r]*36 + cols[r]];
            pb[0] = f2tf(vb[r].x); pb[1] = f2tf(vb[r].y);
            pb[2] = f2tf(vb[r].z); pb[3] = f2tf(vb[r].w);
        }
        __syncthreads();
#pragma unroll
        for (int ks = 0; ks < 4; ks++) {
            unsigned a[4][4], b[4][2];
#pragma unroll
            for (int mt = 0; mt < 4; mt++) {
                int r0 = (wm*64 + mt*16 + g)*36 + ks*8 + t4;
                a[mt][0] = As[r0];       a[mt][1] = As[r0 + 8*36];
                a[mt][2] = As[r0 + 4];   a[mt][3] = As[r0 + 8*36 + 4];
            }
#pragma unroll
            for (int nt = 0; nt < 4; nt++) {
                int r0 = (wn*32 + nt*8 + g)*36 + ks*8 + t4;
                b[nt][0] = Bs[r0]; b[nt][1] = Bs[r0 + 4];
            }
#pragma unroll
            for (int mt = 0; mt < 4; mt++)
#pragma unroll
                for (int nt = 0; nt < 4; nt++) mma8(acc[mt][nt], a[mt], b[nt]);
        }
        __syncthreads();
    }

#pragma unroll
    for (int mt = 0; mt < 4; mt++) {
        int m0 = bm*128 + wm*64 + mt*16 + g;
#pragma unroll
        for (int nt = 0; nt < 4; nt++) {
            int n0 = bn*128 + wn*32 + nt*8 + 2*t4;
            if (EPI == 0) {
                *(float2*)(out + (size_t)m0*CD + n0)     = make_float2(acc[mt][nt][0], acc[mt][nt][1]);
                *(float2*)(out + (size_t)(m0+8)*CD + n0) = make_float2(acc[mt][nt][2], acc[mt][nt][3]);
            } else {
                scatter_qkv(m0,   n0, acc[mt][nt][0], acc[mt][nt][1], qsc, ksc);
                scatter_qkv(m0+8, n0, acc[mt][nt][2], acc[mt][nt][3], qsc, ksc);
            }
        }
    }
}

// =================================================================
// RoPE in place on g_q / g_k (first 16 dims of each head)
// =================================================================
__global__ void rope_kernel(const float* __restrict__ cs, const float* __restrict__ sn) {
    int idx = blockIdx.x*blockDim.x + threadIdx.x;
    const int totQ = CB*CNH*CT*CHALF;
    const int tot  = totQ + CB*CNKV*CT*CHALF;
    if (idx >= tot) return;
    float* base = g_q;
    int li = idx;
    if (idx >= totQ) { base = g_k; li = idx - totQ; }
    int i  = li & 7;
    int t  = (li >> 3) & (CT - 1);
    int rh = li >> 14;
    float* p = base + ((size_t)rh*CT + t)*CHD;
    float c = cs[t*CHALF + i], s = sn[t*CHALF + i];
    float x1 = p[i], x2 = p[i + CHALF];
    p[i]         = x1*c - x2*s;
    p[i + CHALF] = x1*s + x2*c;
}

// =================================================================
// Flash attention (tf32 tensor cores) + fused v-projection epilogue.
// 64q x 64k tiles, 128 threads (4 warps), warp = one m16 row block.
// =================================================================
__global__ __launch_bounds__(128) void attn_tc() {
    extern __shared__ unsigned sm[];
    unsigned* Qs = sm;                 // [64][68]
    unsigned* Ks = sm + 64*68;         // [64][68]
    unsigned* Ps = Ks + 64*68;         // [64][68]
    unsigned* Vt = Ps + 64*68;         // [64][69]  (V transposed: [d][t])

    const int tid = threadIdx.x, lane = tid & 31, warp = tid >> 5;
    const int g = lane >> 2, t4 = lane & 3;
    const int qb = blockIdx.x, h = blockIdx.y, b = blockIdx.z;
    const int kvh = h / CGROUPS;
    const int w16 = warp * 16;
    const float* qptr  = g_q + (((size_t)b*CNH + h)*CT + (size_t)qb*64)*CHD;
    const float* kbase = g_k + ((size_t)b*CNKV + kvh)*CT*CHD;
    const float* vbase = g_v + ((size_t)b*CNKV + kvh)*CT*CHD;

    // load Q tile (softmax scale folded), tf32-rounded once
#pragma unroll
    for (int r = 0; r < 8; r++) {
        int idx = tid + 128*r, row = idx >> 4, c4 = (idx & 15) << 2;
        float4 v = *(const float4*)(qptr + row*CHD + c4);
        unsigned* p = &Qs[row*68 + c4];
        p[0] = f2tf(v.x*0.125f); p[1] = f2tf(v.y*0.125f);
        p[2] = f2tf(v.z*0.125f); p[3] = f2tf(v.w*0.125f);
    }

    float mst[2] = {-1e30f, -1e30f}, lst[2] = {0.f, 0.f};
    float o[8][4];
#pragma unroll
    for (int dt = 0; dt < 8; dt++)
#pragma unroll
        for (int c = 0; c < 4; c++) o[dt][c] = 0.f;

    for (int jb = 0; jb <= qb; jb++) {
        __syncthreads();   // Q ready (first iter) / prev PV done with Ks,Ps,Vt
#pragma unroll
        for (int r = 0; r < 8; r++) {
            int idx = tid + 128*r, row = idx >> 4, c4 = (idx & 15) << 2;
            float4 kv = *(const float4*)(kbase + (size_t)(jb*64 + row)*CHD + c4);
            unsigned* p = &Ks[row*68 + c4];
            p[0] = f2tf(kv.x); p[1] = f2tf(kv.y); p[2] = f2tf(kv.z); p[3] = f2tf(kv.w);
            float4 vv = *(const float4*)(vbase + (size_t)(jb*64 + row)*CHD + c4);
            Vt[(c4+0)*69 + row] = f2tf(vv.x);
            Vt[(c4+1)*69 + row] = f2tf(vv.y);
            Vt[(c4+2)*69 + row] = f2tf(vv.z);
            Vt[(c4+3)*69 + row] = f2tf(vv.w);
        }
        __syncthreads();

        // S = Q K^T  (warp: m16 x n64)
        float s[8][4];
#pragma unroll
        for (int nt = 0; nt < 8; nt++)
#pragma unroll
            for (int c = 0; c < 4; c++) s[nt][c] = 0.f;
#pragma unroll
        for (int ks = 0; ks < 8; ks++) {
            unsigned a[4];
            int ar = (w16 + g)*68 + ks*8 + t4;
            a[0] = Qs[ar]; a[1] = Qs[ar + 8*68]; a[2] = Qs[ar + 4]; a[3] = Qs[ar + 8*68 + 4];
#pragma unroll
            for (int nt = 0; nt < 8; nt++) {
                unsigned bb[2];
                int br = (nt*8 + g)*68 + ks*8 + t4;
                bb[0] = Ks[br]; bb[1] = Ks[br + 4];
                mma8(s[nt], a, bb);
            }
        }

        if (jb == qb) {   // causal mask on diagonal tile (local coords valid)
            int qr0 = w16 + g, qr1 = qr0 + 8;
#pragma unroll
            for (int nt = 0; nt < 8; nt++) {
                int kc = nt*8 + 2*t4;
                if (kc     > qr0) s[nt][0] = -1e30f;
                if (kc + 1 > qr0) s[nt][1] = -1e30f;
                if (kc     > qr1) s[nt][2] = -1e30f;
                if (kc + 1 > qr1) s[nt][3] = -1e30f;
            }
        }

        // online softmax (rows g and g+8; reduce over 4-lane group)
        float mx0 = -1e30f, mx1 = -1e30f;
#pragma unroll
        for (int nt = 0; nt < 8; nt++) {
            mx0 = fmaxf(mx0, fmaxf(s[nt][0], s[nt][1]));
            mx1 = fmaxf(mx1, fmaxf(s[nt][2], s[nt][3]));
        }
        mx0 = fmaxf(mx0, __shfl_xor_sync(0xffffffffu, mx0, 1));
        mx0 = fmaxf(mx0, __shfl_xor_sync(0xffffffffu, mx0, 2));
        mx1 = fmaxf(mx1, __shfl_xor_sync(0xffffffffu, mx1, 1));
        mx1 = fmaxf(mx1, __shfl_xor_sync(0xffffffffu, mx1, 2));
        float mn0 = fmaxf(mst[0], mx0), mn1 = fmaxf(mst[1], mx1);
        float al0 = __expf(mst[0] - mn0), al1 = __expf(mst[1] - mn1);
        mst[0] = mn0; mst[1] = mn1;
        float rs0 = 0.f, rs1 = 0.f;
#pragma unroll
        for (int nt = 0; nt < 8; nt++) {
            s[nt][0] = __expf(s[nt][0] - mn0); rs0 += s[nt][0];
            s[nt][1] = __expf(s[nt][1] - mn0); rs0 += s[nt][1];
            s[nt][2] = __expf(s[nt][2] - mn1); rs1 += s[nt][2];
            s[nt][3] = __expf(s[nt][3] - mn1); rs1 += s[nt][3];
        }
        rs0 += __shfl_xor_sync(0xffffffffu, rs0, 1);
        rs0 += __shfl_xor_sync(0xffffffffu, rs0, 2);
        rs1 += __shfl_xor_sync(0xffffffffu, rs1, 1);
        rs1 += __shfl_xor_sync(0xffffffffu, rs1, 2);
        lst[0] = lst[0]*al0 + rs0;
        lst[1] = lst[1]*al1 + rs1;
#pragma unroll
        for (int dt = 0; dt < 8; dt++) {
            o[dt][0] *= al0; o[dt][1] *= al0;
            o[dt][2] *= al1; o[dt][3] *= al1;
        }

        // write P (tf32) to shared
#pragma unroll
        for (int nt = 0; nt < 8; nt++) {
            unsigned long long p0 = (unsigned long long)f2tf(s[nt][0])
                                  | ((unsigned long long)f2tf(s[nt][1]) << 32);
            unsigned long long p1 = (unsigned long long)f2tf(s[nt][2])
                                  | ((unsigned long long)f2tf(s[nt][3]) << 32);
            *(unsigned long long*)&Ps[(w16 + g    )*68 + nt*8 + 2*t4] = p0;
            *(unsigned long long*)&Ps[(w16 + g + 8)*68 + nt*8 + 2*t4] = p1;
        }
        __syncthreads();

        // O += P V   (warp: m16 x d64)
#pragma unroll
        for (int ks = 0; ks < 8; ks++) {
            unsigned a[4];
            int ar = (w16 + g)*68 + ks*8 + t4;
            a[0] = Ps[ar]; a[1] = Ps[ar + 8*68]; a[2] = Ps[ar + 4]; a[3] = Ps[ar + 8*68 + 4];
#pragma unroll
            for (int dt = 0; dt < 8; dt++) {
                unsigned bb[2];
                int br = (dt*8 + g)*69 + ks*8 + t4;
                bb[0] = Vt[br]; bb[1] = Vt[br + 4];
                mma8(o[dt], a, bb);
            }
        }
    }

    // epilogue: normalize + subtract projection onto v[t]
#pragma unroll
    for (int rr = 0; rr < 2; rr++) {
        int t = qb*64 + w16 + g + rr*8;
        float inv = 1.f / lst[rr];
        float ov[8][2];
        float pd = 0.f, pn = 0.f;
#pragma unroll
        for (int dt = 0; dt < 8; dt++) {
            float2 vv = *(const float2*)(vbase + (size_t)t*CHD + dt*8 + 2*t4);
            float o0 = o[dt][rr*2 + 0]*inv, o1 = o[dt][rr*2 + 1]*inv;
            ov[dt][0] = o0; ov[dt][1] = o1;
            pd += o0*vv.x + o1*vv.y;
            pn += vv.x*vv.x + vv.y*vv.y;
        }
        pd += __shfl_xor_sync(0xffffffffu, pd, 1);
        pd += __shfl_xor_sync(0xffffffffu, pd, 2);
        pn += __shfl_xor_sync(0xffffffffu, pn, 1);
        pn += __shfl_xor_sync(0xffffffffu, pn, 2);
        float coef = pd / fmaxf(pn, 1e-8f);
        float* dst = g_ao + ((size_t)b*CT + t)*CD + h*CHD;
#pragma unroll
        for (int dt = 0; dt < 8; dt++) {
            float2 vv = *(const float2*)(vbase + (size_t)t*CHD + dt*8 + 2*t4);
            *(float2*)(dst + dt*8 + 2*t4) =
                make_float2(ov[dt][0] - coef*vv.x, ov[dt][1] - coef*vv.y);
        }
    }
}

// =================================================================
extern "C" void kernel_launch(void* const* d_in, const int* in_sizes, int n_in,
                              void* d_out, int out_size) {
    (void)in_sizes; (void)n_in; (void)out_size;
    const float* x    = (const float*)d_in[0];
    const float* cs   = (const float*)d_in[1];
    const float* sn   = (const float*)d_in[2];
    const float* wqkv = (const float*)d_in[4];
    const float* wout = (const float*)d_in[5];
    const float* qsc  = (const float*)d_in[6];
    const float* ksc  = (const float*)d_in[7];
    float* out = (float*)d_out;

    dim3 g1(CNQKV/128, CM/128);           // 12 x 32
    gemm_tc<1><<<g1, 256>>>(x, wqkv, qsc, ksc, nullptr);

    int tot = (CB*CNH + CB*CNKV)*CT*CHALF;
    rope_kernel<<<(tot + 255)/256, 256>>>(cs, sn);

    size_t smemB = (size_t)(64*68*3 + 64*69)*sizeof(unsigned);  // 69888 B
    cudaFuncSetAttribute(attn_tc, cudaFuncAttributeMaxDynamicSharedMemorySize, (int)smemB);
    dim3 g2(CT/64, CNH, CB);              // 32 x 16 x 2
    attn_tc<<<g2, 128, smemB>>>();

    dim3 g3(CD/128, CM/128);              // 8 x 32
    gemm_tc<0><<<g3, 256>>>(nullptr, wout, nullptr, nullptr, out);
}